// round 14
// baseline (speedup 1.0000x reference)
#include <cuda_runtime.h>

// Shapes: re, gt are (B=32, C=10, H=192, W=320) float32, contiguous.
#define NB    32
#define NC    10
#define HW4   15360                 // (192*320)/4 float4 groups per channel
#define N4    (NB*HW4)              // 491520 groups total
#define BLK   256
// Phase block counts (groups/thread): P0:4, P1:2, P2:2, P3:1, P4:4
#define P0_B  480
#define P1_B  960
#define P2_B  960
#define P3_B  1920
#define P4_B  480
#define GRID  (P0_B+P1_B+P2_B+P3_B+P4_B)   // 4800
#define NACC  6
#define EPSF  6e-8f

// [0]=nv [1]=num_pos [2]=focal_sum
// [3]=A (pos+height+const) [4]=B (len1+trig1) [5]=C (len2+trig2)
__device__ float g_part[NACC][GRID];
__device__ unsigned int g_count = 0;   // reset by last block each launch

__device__ __forceinline__ float sl1(float d) {
    float ad = fabsf(d);
    return ad < 1.0f ? 0.5f * d * d : ad - 0.5f;
}

__device__ __forceinline__ float c4(const float4& v, int j) {
    return j == 0 ? v.x : (j == 1 ? v.y : (j == 2 ? v.z : v.w));
}

// float4-unit index of (batch(gi), channel ch, hw(gi))
__device__ __forceinline__ int addr4(int gi, int ch) {
    const int b  = gi / HW4;
    const int hw = gi - b * HW4;
    return b * (NC * HW4) + ch * HW4 + hw;
}

__global__ void __launch_bounds__(BLK, 4)
loss_kernel(const float* __restrict__ re, const float* __restrict__ gt,
            float* __restrict__ out) {
    float a_nv = 0.f, a_np = 0.f, a_f = 0.f, a_A = 0.f, a_B = 0.f, a_C = 0.f;

    const float4* __restrict__ re4 = (const float4*)re;
    const float4* __restrict__ gt4 = (const float4*)gt;

    const int tid = threadIdx.x;
    const int blk = blockIdx.x;

    if (blk < P0_B) {
        // ---- P0: focal / nv / num_pos. 4 groups, 8 loads batched. ----
        const int tt = blk * BLK + tid;                 // 0..122879
        int gi[4]; float4 G0[4], R0[4];
#pragma unroll
        for (int k = 0; k < 4; k++) {
            gi[k] = tt + k * (P0_B * BLK);
            const int a = addr4(gi[k], 0);
            G0[k] = gt4[a];
            R0[k] = re4[a];
        }
#pragma unroll
        for (int k = 0; k < 4; k++) {
#pragma unroll
            for (int j = 0; j < 4; j++) {
                const float g = c4(G0[k], j);
                const float r = c4(R0[k], j);
                const bool  m0  = (g >= 0.0f);
                const bool  pos = (g >= 0.1f);        // FOCAL_THR
                const float safe = fminf(fmaxf(r, 1e-6f), 1.0f - 1e-6f);
                const float larg = pos ? (safe + EPSF) : (1.0f + EPSF - safe);
                const float lg   = __logf(larg);      // larg > 0 always
                const float d0   = g - r;
                const float om   = 1.0f - g;
                const float om2  = om * om;
                float w = pos ? (d0 * d0) : (r * r * (om2 * om2));
                if (!m0) w = 0.0f;
                a_f -= w * lg;
                if (pos) a_np += 1.0f;
                if (g == 1.0f) a_nv += 1.0f;
            }
        }
    } else if (blk < P0_B + P1_B) {
        // ---- P1: pos loss (ch 1,2). 2 groups x 5 streams = 10 loads. ----
        const int tt = (blk - P0_B) * BLK + tid;        // 0..245759
        float4 G0[2], G1[2], R1[2], G2[2], R2[2];
#pragma unroll
        for (int k = 0; k < 2; k++) {
            const int gi = tt + k * (P1_B * BLK);
            const int a0 = addr4(gi, 0);
            G0[k] = gt4[a0];
            G1[k] = gt4[a0 + 1*HW4]; R1[k] = re4[a0 + 1*HW4];
            G2[k] = gt4[a0 + 2*HW4]; R2[k] = re4[a0 + 2*HW4];
        }
#pragma unroll
        for (int k = 0; k < 2; k++) {
#pragma unroll
            for (int j = 0; j < 4; j++) {
                if (c4(G0[k], j) == 1.0f) {
                    a_A += 0.5f * (sl1(c4(R1[k],j) - c4(G1[k],j))
                                 + sl1(c4(R2[k],j) - c4(G2[k],j)));
                }
            }
        }
    } else if (blk < P0_B + P1_B + P2_B) {
        // ---- P2: length (ch 3,6 straight/crossed). 2 x 5 = 10 loads. ----
        const int tt = (blk - P0_B - P1_B) * BLK + tid;
        float4 G0[2], G3[2], R3[2], G6[2], R6[2];
#pragma unroll
        for (int k = 0; k < 2; k++) {
            const int gi = tt + k * (P2_B * BLK);
            const int a0 = addr4(gi, 0);
            G0[k] = gt4[a0];
            G3[k] = gt4[a0 + 3*HW4]; R3[k] = re4[a0 + 3*HW4];
            G6[k] = gt4[a0 + 6*HW4]; R6[k] = re4[a0 + 6*HW4];
        }
#pragma unroll
        for (int k = 0; k < 2; k++) {
#pragma unroll
            for (int j = 0; j < 4; j++) {
                if (c4(G0[k], j) == 1.0f) {
                    const float r3 = c4(R3[k],j), g3 = c4(G3[k],j);
                    const float r6 = c4(R6[k],j), g6 = c4(G6[k],j);
                    a_B += 0.05f * (sl1(r3 - g3) + sl1(r6 - g6));
                    a_C += 0.05f * (sl1(r3 - g6) + sl1(r6 - g3));
                }
            }
        }
    } else if (blk < P0_B + P1_B + P2_B + P3_B) {
        // ---- P3: trig + const (ch 4,5,7,8). 1 group x 9 streams. ----
        const int gi = (blk - P0_B - P1_B - P2_B) * BLK + tid;  // 0..491519
        const int a0 = addr4(gi, 0);
        const float4 G0 = gt4[a0];
        const float4 G4 = gt4[a0 + 4*HW4], R4 = re4[a0 + 4*HW4];
        const float4 G5 = gt4[a0 + 5*HW4], R5 = re4[a0 + 5*HW4];
        const float4 G7 = gt4[a0 + 7*HW4], R7 = re4[a0 + 7*HW4];
        const float4 G8 = gt4[a0 + 8*HW4], R8 = re4[a0 + 8*HW4];
#pragma unroll
        for (int j = 0; j < 4; j++) {
            if (c4(G0, j) == 1.0f) {
                const float r4 = c4(R4,j), g4 = c4(G4,j);
                const float r5 = c4(R5,j), g5 = c4(G5,j);
                const float r7 = c4(R7,j), g7 = c4(G7,j);
                const float r8 = c4(R8,j), g8 = c4(G8,j);
                const float d44 = r4 - g4, d77 = r7 - g7;
                const float d55 = r5 - g5, d88 = r8 - g8;
                a_B += 0.5f * (d44*d44 + d77*d77 + d55*d55 + d88*d88);
                const float d47 = r4 - g7, d74 = r7 - g4;
                const float d58 = r5 - g8, d85 = r8 - g5;
                a_C += 0.5f * (d47*d47 + d74*d74 + d58*d58 + d85*d85);
                const float c1 = 1.0f - r5*r5 - r4*r4;
                const float c2 = 1.0f - r8*r8 - r7*r7;
                a_A += 0.5f * (c1*c1 + c2*c2);
            }
        }
    } else {
        // ---- P4: height (ch 9). 4 groups x 3 streams = 12 loads. ----
        const int tt = (blk - P0_B - P1_B - P2_B - P3_B) * BLK + tid;
        float4 G0[4], G9[4], R9[4];
#pragma unroll
        for (int k = 0; k < 4; k++) {
            const int gi = tt + k * (P4_B * BLK);
            const int a0 = addr4(gi, 0);
            G0[k] = gt4[a0];
            G9[k] = gt4[a0 + 9*HW4]; R9[k] = re4[a0 + 9*HW4];
        }
#pragma unroll
        for (int k = 0; k < 4; k++) {
#pragma unroll
            for (int j = 0; j < 4; j++) {
                if (c4(G0[k], j) == 1.0f)
                    a_A += 0.1f * sl1(c4(R9[k],j) - c4(G9[k],j));
            }
        }
    }

    // Block reduction: warp shuffle -> shared -> per-block partial slot.
    float acc[NACC] = {a_nv, a_np, a_f, a_A, a_B, a_C};
    __shared__ float sh[BLK/32][NACC];
    const int lane = tid & 31;
    const int warp = tid >> 5;
#pragma unroll
    for (int k = 0; k < NACC; k++) {
        float v = acc[k];
#pragma unroll
        for (int o = 16; o > 0; o >>= 1)
            v += __shfl_down_sync(0xffffffffu, v, o);
        if (lane == 0) sh[warp][k] = v;
    }
    __syncthreads();
    if (tid < NACC) {
        float v = 0.0f;
#pragma unroll
        for (int w = 0; w < BLK/32; w++) v += sh[w][tid];
        g_part[tid][blk] = v;
    }

    // Last-block-done: the final block to arrive reduces all partials.
    __shared__ bool is_last;
    __threadfence();
    __syncthreads();
    if (tid == 0) {
        unsigned int old = atomicAdd(&g_count, 1u);
        is_last = (old == GRID - 1);
    }
    __syncthreads();
    if (!is_last) return;

    __threadfence();   // ensure we see every block's partials

    // 6 warps reduce the 6 accumulators over all 4800 block partials.
    __shared__ float tot[NACC];
    if (warp < NACC) {
        float v = 0.0f;
        for (int j = lane; j < GRID; j += 32) v += g_part[warp][j];
#pragma unroll
        for (int o = 16; o > 0; o >>= 1)
            v += __shfl_down_sync(0xffffffffu, v, o);
        if (lane == 0) tot[warp] = v;
    }
    __syncthreads();

    if (tid == 0) {
        g_count = 0;   // reset for next graph replay

        const float nv      = tot[0];
        const float num_pos = tot[1];
        const float S       = tot[2];
        const float focal = (num_pos == 0.0f) ? S : S / num_pos;
        out[0] = focal + (tot[3] + fminf(tot[4], tot[5])) / nv;
    }
}

extern "C" void kernel_launch(void* const* d_in, const int* in_sizes, int n_in,
                              void* d_out, int out_size) {
    const float* re = (const float*)d_in[0];
    const float* gt = (const float*)d_in[1];
    float* out = (float*)d_out;

    loss_kernel<<<GRID, BLK>>>(re, gt, out);
}

// round 15
// speedup vs baseline: 1.5834x; 1.5834x over previous
#include <cuda_runtime.h>

// Shapes: re, gt are (B=32, C=10, H=192, W=320) float32, contiguous.
#define NB     32
#define NC     10
#define HW4    15360                  // (192*320)/4 float4 groups per channel
#define N4     (NB*HW4)               // 491520 groups total
#define GRID   960
#define BLK    256
#define STRIDE (GRID*BLK)             // 245760 -> exactly 2 groups per thread
#define NACC   11

// [0]=nv [1]=num_pos [2]=pos_term [3]=neg_term [4]=S_pos
// [5]=S_len1 [6]=S_len2 [7]=S_trig1 [8]=S_trig2 [9]=S_const [10]=S_h
__device__ float g_acc[NACC];          // zeroed at load; last block re-zeros
__device__ unsigned int g_count = 0;   // reset by last block each launch

__device__ __forceinline__ float sl1(float d) {
    float ad = fabsf(d);
    return ad < 1.0f ? 0.5f * d * d : ad - 0.5f;
}

__device__ __forceinline__ float c4(const float4& v, int j) {
    return j == 0 ? v.x : (j == 1 ? v.y : (j == 2 ? v.z : v.w));
}

__global__ void __launch_bounds__(BLK)
loss_kernel(const float* __restrict__ re, const float* __restrict__ gt,
            float* __restrict__ out) {
    float acc[NACC];
#pragma unroll
    for (int k = 0; k < NACC; k++) acc[k] = 0.0f;

    const float4* __restrict__ re4 = (const float4*)re;
    const float4* __restrict__ gt4 = (const float4*)gt;

    for (int i = blockIdx.x * blockDim.x + threadIdx.x; i < N4;
         i += gridDim.x * blockDim.x) {
        int b   = i / HW4;
        int hw4 = i - b * HW4;
        int base = b * (NC * HW4) + hw4;   // float4-unit index of (b, c=0, hw)

        float4 G0 = gt4[base];
        float4 R0 = re4[base];

        bool mv[4];
        bool any = false;
#pragma unroll
        for (int j = 0; j < 4; j++) {
            float g = c4(G0, j);
            float r = c4(R0, j);
            bool m = (g == 1.0f);
            mv[j] = m;
            any |= m;
            if (m) acc[0] += 1.0f;
            if (g >= 0.0f) {
                float safe = fminf(fmaxf(r, 1e-6f), 1.0f - 1e-6f);
                if (g >= 0.1f) {   // FOCAL_THR
                    acc[1] += 1.0f;
                    float d = g - r;
                    acc[2] -= d * d * logf(safe + 6e-8f);
                } else {
                    float om  = 1.0f - g;
                    float om2 = om * om;
                    acc[3] -= r * r * logf(1.0f + 6e-8f - safe) * om2 * om2;
                }
            }
        }

        if (any) {
            // pos_loss: channels (1,1),(2,2)
            {
                float4 R1 = re4[base + 1 * HW4], G1 = gt4[base + 1 * HW4];
                float4 R2 = re4[base + 2 * HW4], G2 = gt4[base + 2 * HW4];
#pragma unroll
                for (int j = 0; j < 4; j++) if (mv[j]) {
                    acc[4] += sl1(c4(R1, j) - c4(G1, j))
                            + sl1(c4(R2, j) - c4(G2, j));
                }
            }
            // length v1/v2: channels 3 & 6 (straight and crossed)
            {
                float4 R3 = re4[base + 3 * HW4], G3 = gt4[base + 3 * HW4];
                float4 R6 = re4[base + 6 * HW4], G6 = gt4[base + 6 * HW4];
#pragma unroll
                for (int j = 0; j < 4; j++) if (mv[j]) {
                    float r3 = c4(R3, j), g3 = c4(G3, j);
                    float r6 = c4(R6, j), g6 = c4(G6, j);
                    acc[5] += sl1(r3 - g3) + sl1(r6 - g6);
                    acc[6] += sl1(r3 - g6) + sl1(r6 - g3);
                }
            }
            // trig v1/v2 + const: channels 4,5,7,8
            {
                float4 R4 = re4[base + 4 * HW4], G4 = gt4[base + 4 * HW4];
                float4 R5 = re4[base + 5 * HW4], G5 = gt4[base + 5 * HW4];
                float4 R7 = re4[base + 7 * HW4], G7 = gt4[base + 7 * HW4];
                float4 R8 = re4[base + 8 * HW4], G8 = gt4[base + 8 * HW4];
#pragma unroll
                for (int j = 0; j < 4; j++) if (mv[j]) {
                    float r4 = c4(R4, j), g4 = c4(G4, j);
                    float r5 = c4(R5, j), g5 = c4(G5, j);
                    float r7 = c4(R7, j), g7 = c4(G7, j);
                    float r8 = c4(R8, j), g8 = c4(G8, j);
                    float d44 = r4 - g4, d77 = r7 - g7;
                    float d55 = r5 - g5, d88 = r8 - g8;
                    acc[7] += d44 * d44 + d77 * d77 + d55 * d55 + d88 * d88;
                    float d47 = r4 - g7, d74 = r7 - g4;
                    float d58 = r5 - g8, d85 = r8 - g5;
                    acc[8] += d47 * d47 + d74 * d74 + d58 * d58 + d85 * d85;
                    float c1 = 1.0f - r5 * r5 - r4 * r4;
                    float c2 = 1.0f - r8 * r8 - r7 * r7;
                    acc[9] += c1 * c1 + c2 * c2;
                }
            }
            // height: channel 9
            {
                float4 R9 = re4[base + 9 * HW4], G9 = gt4[base + 9 * HW4];
#pragma unroll
                for (int j = 0; j < 4; j++) if (mv[j]) {
                    acc[10] += sl1(c4(R9, j) - c4(G9, j));
                }
            }
        }
    }

    // Block reduction: warp shuffle -> shared -> atomicAdd into g_acc
    __shared__ float sh[BLK/32][NACC];
    int lane = threadIdx.x & 31;
    int warp = threadIdx.x >> 5;
#pragma unroll
    for (int k = 0; k < NACC; k++) {
        float v = acc[k];
#pragma unroll
        for (int o = 16; o > 0; o >>= 1)
            v += __shfl_down_sync(0xffffffffu, v, o);
        if (lane == 0) sh[warp][k] = v;
    }
    __syncthreads();
    if (threadIdx.x < NACC) {
        float v = 0.0f;
#pragma unroll
        for (int w = 0; w < BLK/32; w++) v += sh[w][threadIdx.x];
        atomicAdd(&g_acc[threadIdx.x], v);
    }

    // Last-block-done: final block computes the output and resets state.
    __shared__ bool is_last;
    __threadfence();
    __syncthreads();
    if (threadIdx.x == 0) {
        unsigned int old = atomicAdd(&g_count, 1u);
        is_last = (old == GRID - 1);
    }
    __syncthreads();
    if (!is_last) return;

    if (threadIdx.x == 0) {
        __threadfence();   // see all blocks' atomics

        float nv       = g_acc[0];
        float num_pos  = g_acc[1];
        float pos_term = g_acc[2];
        float neg_term = g_acc[3];

        float focal = (num_pos == 0.0f) ? neg_term
                                        : (pos_term + neg_term) / num_pos;
        float inv2nv = 1.0f / (2.0f * nv);
        float invnv  = 1.0f / nv;

        float confidence_loss = 1.0f * focal;             // CONF_W
        float pos_loss   = 1.0f * g_acc[4] * inv2nv;      // POS_W
        float len_v1     = 0.1f * g_acc[5] * inv2nv;      // LEN_W
        float len_v2     = 0.1f * g_acc[6] * inv2nv;
        float trig_v1    = 1.0f * g_acc[7] * inv2nv;      // TRIG_W
        float trig_v2    = 1.0f * g_acc[8] * inv2nv;
        float const_loss = 0.5f * g_acc[9] * invnv;       // CONST_W
        float height     = 0.1f * g_acc[10] * invnv;      // LEN_W

        float dims = fminf(len_v1 + trig_v1, len_v2 + trig_v2) + height;
        out[0] = confidence_loss + pos_loss + dims + const_loss;

        // Reset for the next graph replay (deterministic).
#pragma unroll
        for (int k = 0; k < NACC; k++) g_acc[k] = 0.0f;
        g_count = 0;
    }
}

extern "C" void kernel_launch(void* const* d_in, const int* in_sizes, int n_in,
                              void* d_out, int out_size) {
    const float* re = (const float*)d_in[0];
    const float* gt = (const float*)d_in[1];
    float* out = (float*)d_out;

    loss_kernel<<<GRID, BLK>>>(re, gt, out);
}